// round 3
// baseline (speedup 1.0000x reference)
#include <cuda_runtime.h>
#include <cuda_bf16.h>
#include <cstdint>
#include <cstddef>

// ----------------------------------------------------------------------------
// Problem constants
// ----------------------------------------------------------------------------
#define BB   512
#define QQ   32768
#define DD   256
#define ROWL 32769            // 1 + Q
#define NCOMBO 8

__constant__ int d_CI[8] = {0, 0, 0, 1, 1, 2, 2, 3};
__constant__ int d_CJ[8] = {1, 2, 3, 0, 2, 0, 1, 0};

// ----------------------------------------------------------------------------
// Scratch (device globals; no allocation allowed)
// ----------------------------------------------------------------------------
__device__ __align__(16) __nv_bfloat16 g_mem_hi[4u * QQ * DD];   // 64 MB
__device__ __align__(16) __nv_bfloat16 g_mem_lo[4u * QQ * DD];   // 64 MB
__device__ __align__(16) __nv_bfloat16 g_x_hi[4 * BB * DD];
__device__ __align__(16) __nv_bfloat16 g_x_lo[4 * BB * DD];
__device__ float g_norm[4 * BB];
__device__ float g_scale[NCOMBO * BB];

// ----------------------------------------------------------------------------
// PTX helpers (sm_103-safe: mma.sync / ldmatrix / cp.async only)
// ----------------------------------------------------------------------------
__device__ __forceinline__ uint32_t smem_to_u32(const void* p) {
    uint32_t a;
    asm("{ .reg .u64 t; cvta.to.shared.u64 t, %1; cvt.u32.u64 %0, t; }" : "=r"(a) : "l"(p));
    return a;
}

__device__ __forceinline__ void cp_async16(uint32_t saddr, const void* gaddr) {
    asm volatile("cp.async.cg.shared.global [%0], [%1], 16;" :: "r"(saddr), "l"(gaddr));
}
__device__ __forceinline__ void cp_commit() {
    asm volatile("cp.async.commit_group;" ::: "memory");
}
template <int N>
__device__ __forceinline__ void cp_wait() {
    asm volatile("cp.async.wait_group %0;" :: "n"(N) : "memory");
}

__device__ __forceinline__ void ldsm_x4(uint32_t* r, uint32_t addr) {
    asm volatile("ldmatrix.sync.aligned.m8n8.x4.shared.b16 {%0,%1,%2,%3}, [%4];"
                 : "=r"(r[0]), "=r"(r[1]), "=r"(r[2]), "=r"(r[3]) : "r"(addr));
}

__device__ __forceinline__ void mma_bf16(float* d, const uint32_t* a, const uint32_t* b) {
    asm volatile(
        "mma.sync.aligned.m16n8k16.row.col.f32.bf16.bf16.f32 "
        "{%0,%1,%2,%3}, {%4,%5,%6,%7}, {%8,%9}, {%0,%1,%2,%3};"
        : "+f"(d[0]), "+f"(d[1]), "+f"(d[2]), "+f"(d[3])
        : "r"(a[0]), "r"(a[1]), "r"(a[2]), "r"(a[3]), "r"(b[0]), "r"(b[1]));
}

// ----------------------------------------------------------------------------
// Small helpers
// ----------------------------------------------------------------------------
__device__ __forceinline__ uint32_t pack_bf2(__nv_bfloat16 a, __nv_bfloat16 b) {
    return (uint32_t)__bfloat16_as_ushort(a) | ((uint32_t)__bfloat16_as_ushort(b) << 16);
}

__device__ __forceinline__ void split_hilo(float f, __nv_bfloat16& h, __nv_bfloat16& l) {
    h = __float2bfloat16(f);                  // round-to-nearest
    l = __float2bfloat16(f - __bfloat162float(h));
}

__device__ __forceinline__ const float* sel4(int v, const float* a, const float* b,
                                             const float* c, const float* d) {
    return v == 0 ? a : (v == 1 ? b : (v == 2 ? c : d));
}

// ----------------------------------------------------------------------------
// k_norm: per-row L2 norms of the 4 X views (one warp per row)
// ----------------------------------------------------------------------------
__global__ void k_norm(const float* __restrict__ x0, const float* __restrict__ x1,
                       const float* __restrict__ x2, const float* __restrict__ x3) {
    int gw = (blockIdx.x * blockDim.x + threadIdx.x) >> 5;
    int lane = threadIdx.x & 31;
    if (gw >= 4 * BB) return;
    int v = gw >> 9, b = gw & (BB - 1);
    const float* row = sel4(v, x0, x1, x2, x3) + (size_t)b * DD;
    float s = 0.f;
#pragma unroll
    for (int k = 0; k < 8; k++) { float t = row[lane + k * 32]; s += t * t; }
#pragma unroll
    for (int o = 16; o; o >>= 1) s += __shfl_xor_sync(0xffffffffu, s, o);
    if (lane == 0) g_norm[gw] = sqrtf(s);
}

// ----------------------------------------------------------------------------
// k_prep_x: X -> hi/lo bf16 scratch; Y -> tail of new_mem output
// ----------------------------------------------------------------------------
__global__ void k_prep_x(const float* __restrict__ x0, const float* __restrict__ x1,
                         const float* __restrict__ x2, const float* __restrict__ x3,
                         const float* __restrict__ y0, const float* __restrict__ y1,
                         const float* __restrict__ y2, const float* __restrict__ y3,
                         float* __restrict__ out_mem) {
    int v = blockIdx.y;
    int bx = blockIdx.x;
    int t = threadIdx.x;
    if (bx < 128) {
        int idx = bx * 256 + t;
        float4 f = reinterpret_cast<const float4*>(sel4(v, x0, x1, x2, x3))[idx];
        __nv_bfloat16 h0, h1, h2, h3, l0, l1, l2, l3;
        split_hilo(f.x, h0, l0); split_hilo(f.y, h1, l1);
        split_hilo(f.z, h2, l2); split_hilo(f.w, h3, l3);
        uint2 uh; uh.x = pack_bf2(h0, h1); uh.y = pack_bf2(h2, h3);
        uint2 ul; ul.x = pack_bf2(l0, l1); ul.y = pack_bf2(l2, l3);
        reinterpret_cast<uint2*>(g_x_hi)[(size_t)v * 32768 + idx] = uh;
        reinterpret_cast<uint2*>(g_x_lo)[(size_t)v * 32768 + idx] = ul;
    } else {
        int idx = (bx - 128) * 256 + t;
        float4 f = reinterpret_cast<const float4*>(sel4(v, y0, y1, y2, y3))[idx];
        reinterpret_cast<float4*>(out_mem)[(size_t)v * (QQ * DD / 4) + (size_t)(QQ - BB) * (DD / 4) + idx] = f;
    }
}

// ----------------------------------------------------------------------------
// k_self: self-dots (column 0) + per-row scales. One warp per (combo,row).
// ----------------------------------------------------------------------------
__global__ void k_self(const float* __restrict__ x0, const float* __restrict__ x1,
                       const float* __restrict__ x2, const float* __restrict__ x3,
                       float* __restrict__ out) {
    int gw = (blockIdx.x * blockDim.x + threadIdx.x) >> 5;
    int lane = threadIdx.x & 31;
    if (gw >= NCOMBO * BB) return;
    int c = gw >> 9, b = gw & (BB - 1);
    int i = d_CI[c], j = d_CJ[c];
    const float* xi = sel4(i, x0, x1, x2, x3) + (size_t)b * DD;
    const float* xj = sel4(j, x0, x1, x2, x3) + (size_t)b * DD;
    float s = 0.f;
#pragma unroll
    for (int k = 0; k < 8; k++) s += xi[lane + k * 32] * xj[lane + k * 32];
#pragma unroll
    for (int o = 16; o; o >>= 1) s += __shfl_xor_sync(0xffffffffu, s, o);
    if (lane == 0) {
        float sc = 1.0f / (g_norm[i * BB + b] * g_norm[j * BB + b] * 0.07f);
        g_scale[c * BB + b] = sc;
        out[(size_t)c * BB * ROWL + (size_t)b * ROWL] = __expf(s * sc);
    }
}

// ----------------------------------------------------------------------------
// k_prep_mem: Mem -> hi/lo bf16 scratch AND FIFO-shifted new_mem output.
// ----------------------------------------------------------------------------
__global__ void k_prep_mem(const float* __restrict__ m0, const float* __restrict__ m1,
                           const float* __restrict__ m2, const float* __restrict__ m3,
                           float* __restrict__ out_mem) {
    int v = blockIdx.y;
    int idx = blockIdx.x * 256 + threadIdx.x;      // < QQ*DD/4 = 2097152
    const float* mp = sel4(v, m0, m1, m2, m3);
    float4 f = reinterpret_cast<const float4*>(mp)[idx];
    __nv_bfloat16 h0, h1, h2, h3, l0, l1, l2, l3;
    split_hilo(f.x, h0, l0); split_hilo(f.y, h1, l1);
    split_hilo(f.z, h2, l2); split_hilo(f.w, h3, l3);
    uint2 uh; uh.x = pack_bf2(h0, h1); uh.y = pack_bf2(h2, h3);
    uint2 ul; ul.x = pack_bf2(l0, l1); ul.y = pack_bf2(l2, l3);
    size_t base = (size_t)v * (QQ * DD / 4) + idx;
    reinterpret_cast<uint2*>(g_mem_hi)[base] = uh;
    reinterpret_cast<uint2*>(g_mem_lo)[base] = ul;
    if (idx >= BB * (DD / 4)) {
        reinterpret_cast<float4*>(out_mem)[(size_t)v * (QQ * DD / 4) + idx - BB * (DD / 4)] = f;
    }
}

// ----------------------------------------------------------------------------
// k_gemm: mma.sync bf16 hi/lo split GEMM + exp epilogue.
// Block tile M=128 x N=128, K=256 in 4 chunks of 64, cp.async double-buffered.
// 8 warps: 2 (m) x 4 (n); warp tile 64x32.
// Smem tile layout: 128 rows x 64 bf16, padded row stride 72 bf16 (144 B).
// ----------------------------------------------------------------------------
#define TS_ROWB   144
#define TILE_B    (128 * TS_ROWB)          // 18432
#define BUF_B     (4 * TILE_B)             // 73728 (Ah, Al, Bh, Bl)
#define GEMM_SMEM (2 * BUF_B)              // 147456

__global__ void __launch_bounds__(256) k_gemm(float* __restrict__ out) {
    extern __shared__ char smem[];
    const uint32_t sb = smem_to_u32(smem);
    const int tid = threadIdx.x, lane = tid & 31, wid = tid >> 5;
    const int wm = wid & 1, wn = wid >> 1;
    const int cm = blockIdx.x;
    const int c = cm >> 2, mtile = cm & 3, ntile = blockIdx.y;
    const int i = d_CI[c], j = d_CJ[c];

    const __nv_bfloat16* src[4];
    src[0] = g_x_hi   + ((size_t)i * BB + mtile * 128) * DD;
    src[1] = g_x_lo   + ((size_t)i * BB + mtile * 128) * DD;
    src[2] = g_mem_hi + ((size_t)j * QQ + (size_t)ntile * 128) * DD;
    src[3] = g_mem_lo + ((size_t)j * QQ + (size_t)ntile * 128) * DD;

    // per-thread load slots: 4 uint4 per tile, row = idx/8, seg = idx%8
    const int l_row[4] = { (tid + 0 * 256) >> 3, (tid + 1 * 256) >> 3,
                           (tid + 2 * 256) >> 3, (tid + 3 * 256) >> 3 };
    const int l_seg = tid & 7;

    auto issue_chunk = [&](int kc, int buf) {
        uint32_t sbase = sb + buf * BUF_B;
#pragma unroll
        for (int t = 0; t < 4; t++) {
#pragma unroll
            for (int r = 0; r < 4; r++) {
                const __nv_bfloat16* g = src[t] + (size_t)l_row[r] * DD + kc * 64 + l_seg * 8;
                uint32_t s = sbase + t * TILE_B + l_row[r] * TS_ROWB + l_seg * 16;
                cp_async16(s, g);
            }
        }
        cp_commit();
    };

    float acc[4][4][4];
#pragma unroll
    for (int a = 0; a < 4; a++)
#pragma unroll
        for (int b = 0; b < 4; b++)
#pragma unroll
            for (int k = 0; k < 4; k++) acc[a][b][k] = 0.f;

    // ldmatrix base addresses (within a buffer)
    // A: lane i -> row (lane%16), chunk (lane/16)*16B
    const uint32_t a_lane_off = (uint32_t)((lane & 15) * TS_ROWB + (lane >> 4) * 16);
    // B: lane i -> row (lane%8) + (lane/16)*8, chunk ((lane/8)%2)*16B
    const uint32_t b_lane_off = (uint32_t)(((lane & 7) + ((lane >> 4) << 3)) * TS_ROWB
                                           + (((lane >> 3) & 1) * 16));

    issue_chunk(0, 0);

#pragma unroll 1
    for (int kc = 0; kc < 4; kc++) {
        if (kc < 3) issue_chunk(kc + 1, (kc + 1) & 1);
        if (kc < 3) cp_wait<1>(); else cp_wait<0>();
        __syncthreads();

        const uint32_t bufb = sb + (kc & 1) * BUF_B;
        const uint32_t aH = bufb + 0 * TILE_B + (wm * 64) * TS_ROWB + a_lane_off;
        const uint32_t aL = bufb + 1 * TILE_B + (wm * 64) * TS_ROWB + a_lane_off;
        const uint32_t bH = bufb + 2 * TILE_B + (wn * 32) * TS_ROWB + b_lane_off;
        const uint32_t bL = bufb + 3 * TILE_B + (wn * 32) * TS_ROWB + b_lane_off;

#pragma unroll
        for (int step = 0; step < 4; step++) {
            const uint32_t koff = step * 32;   // 16 bf16 = 32 bytes
            uint32_t bh[8], bl[8];
            ldsm_x4(bh + 0, bH + koff);                       // n 0-15
            ldsm_x4(bh + 4, bH + 16 * TS_ROWB + koff);        // n 16-31
            ldsm_x4(bl + 0, bL + koff);
            ldsm_x4(bl + 4, bL + 16 * TS_ROWB + koff);
#pragma unroll
            for (int mi = 0; mi < 4; mi++) {
                uint32_t ah[4], al[4];
                ldsm_x4(ah, aH + mi * 16 * TS_ROWB + koff);
                ldsm_x4(al, aL + mi * 16 * TS_ROWB + koff);
#pragma unroll
                for (int ni = 0; ni < 4; ni++) {
                    mma_bf16(acc[mi][ni], ah, bh + ni * 2);
                    mma_bf16(acc[mi][ni], ah, bl + ni * 2);
                    mma_bf16(acc[mi][ni], al, bh + ni * 2);
                }
            }
        }
        __syncthreads();
    }

    // Epilogue: exp(d * scale_row) -> out
    const int r0 = lane >> 2;
    const int cpair = (lane & 3) * 2;
#pragma unroll
    for (int mi = 0; mi < 4; mi++) {
        const int grow0 = mtile * 128 + wm * 64 + mi * 16 + r0;
        const float scl0 = g_scale[c * BB + grow0];
        const float scl1 = g_scale[c * BB + grow0 + 8];
        const size_t base0 = ((size_t)c * BB + grow0) * ROWL;
        const size_t base1 = base0 + (size_t)8 * ROWL;
#pragma unroll
        for (int ni = 0; ni < 4; ni++) {
            const size_t col = 1 + (size_t)ntile * 128 + wn * 32 + ni * 8 + cpair;
            out[base0 + col + 0] = __expf(acc[mi][ni][0] * scl0);
            out[base0 + col + 1] = __expf(acc[mi][ni][1] * scl0);
            out[base1 + col + 0] = __expf(acc[mi][ni][2] * scl1);
            out[base1 + col + 1] = __expf(acc[mi][ni][3] * scl1);
        }
    }
}

// ----------------------------------------------------------------------------
// kernel_launch
// Input order detected from in_sizes: setup_inputs() builds the dict
// interleaved (x0,y0,mem0, x1,y1,mem1, ...) -> in_sizes[2] == Q*D.
// Grouped fallback (x0..x3,y0..y3,mem0..mem3) -> in_sizes[2] == B*D.
// ----------------------------------------------------------------------------
extern "C" void kernel_launch(void* const* d_in, const int* in_sizes, int n_in,
                              void* d_out, int out_size) {
    (void)n_in; (void)out_size;
    const float* x[4]; const float* y[4]; const float* m[4];
    const bool interleaved = (in_sizes[2] == QQ * DD);
    for (int v = 0; v < 4; v++) {
        if (interleaved) {
            x[v] = (const float*)d_in[3 * v + 0];
            y[v] = (const float*)d_in[3 * v + 1];
            m[v] = (const float*)d_in[3 * v + 2];
        } else {
            x[v] = (const float*)d_in[v];
            y[v] = (const float*)d_in[4 + v];
            m[v] = (const float*)d_in[8 + v];
        }
    }
    float* out = (float*)d_out;
    float* out_mem = out + (size_t)NCOMBO * BB * ROWL;

    cudaFuncSetAttribute(k_gemm, cudaFuncAttributeMaxDynamicSharedMemorySize, GEMM_SMEM);

    k_norm<<<256, 256>>>(x[0], x[1], x[2], x[3]);
    k_prep_x<<<dim3(256, 4), 256>>>(x[0], x[1], x[2], x[3],
                                    y[0], y[1], y[2], y[3], out_mem);
    k_self<<<512, 256>>>(x[0], x[1], x[2], x[3], out);
    k_prep_mem<<<dim3(8192, 4), 256>>>(m[0], m[1], m[2], m[3], out_mem);
    k_gemm<<<dim3(32, 256), 256, GEMM_SMEM>>>(out);
}